// round 4
// baseline (speedup 1.0000x reference)
#include <cuda_runtime.h>
#include <cuda_bf16.h>

// GlobalAttentionLayer, single fused pass (R4).
// pooled[b] = sum_n e^{g_n} * (states_n @ Wo + bo) / (sum_n e^{g_n} + eps)
//
// R4 changes vs R3:
//  - ga_zero launch removed: accumulators are zero at module load (.bss) and
//    ga_finalize re-zeros them after reading, so the invariant "acc == 0 on
//    entry to ga_main" holds for every call (incl. graph replays).
//  - x4 unroll, 8 LDG.128 batched up front (MLP ~8/warp), scalar FMA only.
//    One seg check per 4 nodes (ids sorted -> seg[n+3]==cur covers all 4).
//  - __launch_bounds__(256,3): allow ~84 regs, 3 CTAs/SM, more in-flight loads.
//
// Inputs (metadata order):
//   d_in[0] states  float32 [N, 256]
//   d_in[1] seg_ids int32   [N]   (sorted)
//   d_in[2] Wg float32 [256,1]   d_in[3] bg float32 [1]
//   d_in[4] Wo float32 [256,2]   d_in[5] bo float32 [2]
// Output: float32 [B, 2], B = out_size/2

#define NBLOCKS  592
#define NTHREADS 256
#define MAXB     1024

__device__ float g_accS [MAXB];   // zero-initialized (.bss); finalize re-zeros
__device__ float g_accV0[MAXB];
__device__ float g_accV1[MAXB];

__global__ __launch_bounds__(NTHREADS, 3) void ga_main(
    const float* __restrict__ states,
    const int*   __restrict__ seg,
    const float* __restrict__ Wg,
    const float* __restrict__ bg,
    const float* __restrict__ Wo,
    const float* __restrict__ bo,
    int N)
{
    const int lane   = threadIdx.x & 31;
    const int gwarp  = (blockIdx.x * blockDim.x + threadIdx.x) >> 5;
    const int nwarps = (gridDim.x * blockDim.x) >> 5;
    const int chunk  = (N + nwarps - 1) / nwarps;
    const int start  = gwarp * chunk;
    const int end    = min(start + chunk, N);
    if (start >= end) return;

    // Per-lane slice of the weight vectors: columns [lane*8, lane*8+8)
    const int c0 = lane * 8;
    float wg[8], wo0[8], wo1[8];
#pragma unroll
    for (int j = 0; j < 8; j++) {
        wg [j] = Wg[c0 + j];
        wo0[j] = Wo[(c0 + j) * 2 + 0];
        wo1[j] = Wo[(c0 + j) * 2 + 1];
    }
    const float bgv = bg[0];
    const float bo0 = bo[0];
    const float bo1 = bo[1];

    const float4* base = reinterpret_cast<const float4*>(states);

    int   cur = seg[start];
    float aS  = 0.0f;                 // sum of e (lane-uniform)
    float aV0 = 0.0f, aV1 = 0.0f;     // per-lane partial sums of e * p_lane

    // Flush: butterfly-reduce per-lane value partials, then 3 atomics.
    //   sum_n e_n*(p0_n + bo0) = warp_sum(aV0) + bo0 * aS
#define FLUSH(SEGID)                                                        \
    do {                                                                    \
        float _v0 = aV0, _v1 = aV1;                                         \
        _Pragma("unroll")                                                   \
        for (int _o = 16; _o; _o >>= 1) {                                   \
            _v0 += __shfl_xor_sync(0xFFFFFFFFu, _v0, _o);                   \
            _v1 += __shfl_xor_sync(0xFFFFFFFFu, _v1, _o);                   \
        }                                                                   \
        if (lane == 0) {                                                    \
            atomicAdd(&g_accS [SEGID], aS);                                 \
            atomicAdd(&g_accV0[SEGID], fmaf(bo0, aS, _v0));                 \
            atomicAdd(&g_accV1[SEGID], fmaf(bo1, aS, _v1));                 \
        }                                                                   \
        aS = 0.0f; aV0 = 0.0f; aV1 = 0.0f;                                  \
    } while (0)

    int n = start;

    // ---- main loop: 4 nodes/iter, all 8 row loads batched up front ----
    for (; n + 4 <= end; n += 4) {
        float4 xa[4], xb[4];
#pragma unroll
        for (int k = 0; k < 4; k++) {
            const float4* row = base + (size_t)(n + k) * 64 + lane * 2;
            xa[k] = row[0];
            xb[k] = row[1];
        }
        int svL = seg[n + 3];   // sorted: svL == cur implies all 4 ids == cur

        float g[4], p0[4], p1[4];
#pragma unroll
        for (int k = 0; k < 4; k++) {
            float x[8] = {xa[k].x, xa[k].y, xa[k].z, xa[k].w,
                          xb[k].x, xb[k].y, xb[k].z, xb[k].w};
            float gk = 0.f, p0k = 0.f, p1k = 0.f;
#pragma unroll
            for (int j = 0; j < 8; j++) {
                gk  = fmaf(x[j], wg [j], gk);
                p0k = fmaf(x[j], wo0[j], p0k);
                p1k = fmaf(x[j], wo1[j], p1k);
            }
            g[k] = gk; p0[k] = p0k; p1[k] = p1k;
        }

        // 4 independent butterfly chains, interleaved (gates only)
#pragma unroll
        for (int off = 16; off; off >>= 1) {
#pragma unroll
            for (int k = 0; k < 4; k++)
                g[k] += __shfl_xor_sync(0xFFFFFFFFu, g[k], off);
        }

        float e[4];
#pragma unroll
        for (int k = 0; k < 4; k++)
            e[k] = __expf(g[k] + bgv);

        if (svL != cur) {                    // rare: <=63 boundaries total
#pragma unroll
            for (int k = 0; k < 4; k++) {
                int s = seg[n + k];
                if (s != cur) { FLUSH(cur); cur = s; }
                aS += e[k];
                aV0 = fmaf(e[k], p0[k], aV0);
                aV1 = fmaf(e[k], p1[k], aV1);
            }
        } else {                             // hot path
            aS += (e[0] + e[1]) + (e[2] + e[3]);
            aV0 = fmaf(e[0], p0[0], fmaf(e[1], p0[1],
                  fmaf(e[2], p0[2], fmaf(e[3], p0[3], aV0))));
            aV1 = fmaf(e[0], p1[0], fmaf(e[1], p1[1],
                  fmaf(e[2], p1[2], fmaf(e[3], p1[3], aV1))));
        }
    }

    // ---- tail (<4 nodes) ----
    for (; n < end; n++) {
        const float4* row = base + (size_t)n * 64 + lane * 2;
        float4 xa = row[0];
        float4 xb = row[1];
        int s = seg[n];

        float x[8] = {xa.x, xa.y, xa.z, xa.w, xb.x, xb.y, xb.z, xb.w};
        float gk = 0.f, p0k = 0.f, p1k = 0.f;
#pragma unroll
        for (int j = 0; j < 8; j++) {
            gk  = fmaf(x[j], wg [j], gk);
            p0k = fmaf(x[j], wo0[j], p0k);
            p1k = fmaf(x[j], wo1[j], p1k);
        }
#pragma unroll
        for (int off = 16; off; off >>= 1)
            gk += __shfl_xor_sync(0xFFFFFFFFu, gk, off);

        float ek = __expf(gk + bgv);
        if (s != cur) { FLUSH(cur); cur = s; }
        aS += ek;
        aV0 = fmaf(ek, p0k, aV0);
        aV1 = fmaf(ek, p1k, aV1);
    }

    FLUSH(cur);
#undef FLUSH
}

__global__ void ga_finalize(float* __restrict__ out, int B) {
    int b = blockIdx.x * blockDim.x + threadIdx.x;
    if (b < B) {
        float s  = g_accS [b];
        float v0 = g_accV0[b];
        float v1 = g_accV1[b];
        float d  = s + 1e-16f;
        out[2 * b + 0] = v0 / d;
        out[2 * b + 1] = v1 / d;
        // restore the "accumulators are zero" invariant for the next call
        g_accS [b] = 0.0f;
        g_accV0[b] = 0.0f;
        g_accV1[b] = 0.0f;
    }
}

extern "C" void kernel_launch(void* const* d_in, const int* in_sizes, int n_in,
                              void* d_out, int out_size)
{
    const float* states = (const float*)d_in[0];
    const int*   seg    = (const int*)  d_in[1];
    const float* Wg     = (const float*)d_in[2];
    const float* bg     = (const float*)d_in[3];
    const float* Wo     = (const float*)d_in[4];
    const float* bo     = (const float*)d_in[5];
    float*       out    = (float*)d_out;

    const int N = in_sizes[1];
    const int B = out_size / 2;

    ga_main<<<NBLOCKS, NTHREADS>>>(states, seg, Wg, bg, Wo, bo, N);
    ga_finalize<<<(B + 255) / 256, 256>>>(out, B);
}

// round 5
// speedup vs baseline: 1.0766x; 1.0766x over previous
#include <cuda_runtime.h>
#include <cuda_bf16.h>

// GlobalAttentionLayer, single fused pass (R5).
// pooled[b] = sum_n e^{g_n} * (states_n @ Wo + bo) / (sum_n e^{g_n} + eps)
//
// R5 = R3 main kernel EXACTLY (x2 unroll, 4 front-batched LDG.128, deferred
// value reduction, plain __launch_bounds__(256)) + ga_zero launch removed:
// accumulators are zero at module load (.bss) and ga_finalize re-zeros them
// after reading, so "acc == 0 on entry to ga_main" holds for every call,
// including CUDA-graph replays. x4 unroll is confirmed-regressive (R2, R4).
//
// Inputs (metadata order):
//   d_in[0] states  float32 [N, 256]
//   d_in[1] seg_ids int32   [N]   (sorted)
//   d_in[2] Wg float32 [256,1]   d_in[3] bg float32 [1]
//   d_in[4] Wo float32 [256,2]   d_in[5] bo float32 [2]
// Output: float32 [B, 2], B = out_size/2

#define NBLOCKS  592
#define NTHREADS 256
#define MAXB     1024

__device__ float g_accS [MAXB];   // zero-initialized (.bss); finalize re-zeros
__device__ float g_accV0[MAXB];
__device__ float g_accV1[MAXB];

__global__ __launch_bounds__(NTHREADS) void ga_main(
    const float* __restrict__ states,
    const int*   __restrict__ seg,
    const float* __restrict__ Wg,
    const float* __restrict__ bg,
    const float* __restrict__ Wo,
    const float* __restrict__ bo,
    int N)
{
    const int lane   = threadIdx.x & 31;
    const int gwarp  = (blockIdx.x * blockDim.x + threadIdx.x) >> 5;
    const int nwarps = (gridDim.x * blockDim.x) >> 5;
    const int chunk  = (N + nwarps - 1) / nwarps;
    const int start  = gwarp * chunk;
    const int end    = min(start + chunk, N);
    if (start >= end) return;

    // Per-lane slice of the weight vectors: columns [lane*8, lane*8+8)
    const int c0 = lane * 8;
    float wg[8], wo0[8], wo1[8];
#pragma unroll
    for (int j = 0; j < 8; j++) {
        wg [j] = Wg[c0 + j];
        wo0[j] = Wo[(c0 + j) * 2 + 0];
        wo1[j] = Wo[(c0 + j) * 2 + 1];
    }
    const float bgv = bg[0];
    const float bo0 = bo[0];
    const float bo1 = bo[1];

    const float4* base = reinterpret_cast<const float4*>(states);

    int   cur = seg[start];
    float aS  = 0.0f;                 // sum of e (lane-uniform)
    float aV0 = 0.0f, aV1 = 0.0f;     // per-lane partial sums of e * p_lane

    // Flush: reduce per-lane value partials across the warp, then atomic.
    //   sum_n e_n*(p0_n + bo0) = warp_sum(aV0) + bo0 * aS
#define FLUSH(SEGID)                                                        \
    do {                                                                    \
        float _v0 = aV0, _v1 = aV1;                                         \
        _Pragma("unroll")                                                   \
        for (int _o = 16; _o; _o >>= 1) {                                   \
            _v0 += __shfl_xor_sync(0xFFFFFFFFu, _v0, _o);                   \
            _v1 += __shfl_xor_sync(0xFFFFFFFFu, _v1, _o);                   \
        }                                                                   \
        if (lane == 0) {                                                    \
            atomicAdd(&g_accS [SEGID], aS);                                 \
            atomicAdd(&g_accV0[SEGID], fmaf(bo0, aS, _v0));                 \
            atomicAdd(&g_accV1[SEGID], fmaf(bo1, aS, _v1));                 \
        }                                                                   \
        aS = 0.0f; aV0 = 0.0f; aV1 = 0.0f;                                  \
    } while (0)

    int n = start;

    // ---- main loop: 2 nodes/iter, all 4 row loads batched up front ----
    for (; n + 2 <= end; n += 2) {
        const float4* r0 = base + (size_t)(n + 0) * 64 + lane * 2;
        const float4* r1 = base + (size_t)(n + 1) * 64 + lane * 2;
        float4 xa0 = r0[0];
        float4 xb0 = r0[1];
        float4 xa1 = r1[0];
        float4 xb1 = r1[1];
        int sv1 = seg[n + 1];   // sorted: sv1 == cur implies seg[n] == cur

        float x0[8] = {xa0.x, xa0.y, xa0.z, xa0.w, xb0.x, xb0.y, xb0.z, xb0.w};
        float x1[8] = {xa1.x, xa1.y, xa1.z, xa1.w, xb1.x, xb1.y, xb1.z, xb1.w};

        float g0 = 0.f, p00 = 0.f, p10 = 0.f;
        float g1 = 0.f, p01 = 0.f, p11 = 0.f;
#pragma unroll
        for (int j = 0; j < 8; j++) {
            g0  = fmaf(x0[j], wg [j], g0);
            g1  = fmaf(x1[j], wg [j], g1);
            p00 = fmaf(x0[j], wo0[j], p00);
            p01 = fmaf(x1[j], wo0[j], p01);
            p10 = fmaf(x0[j], wo1[j], p10);
            p11 = fmaf(x1[j], wo1[j], p11);
        }

        // Two independent butterfly chains, interleaved (only the gates)
#pragma unroll
        for (int off = 16; off; off >>= 1) {
            g0 += __shfl_xor_sync(0xFFFFFFFFu, g0, off);
            g1 += __shfl_xor_sync(0xFFFFFFFFu, g1, off);
        }

        float e0 = __expf(g0 + bgv);
        float e1 = __expf(g1 + bgv);

        if (sv1 != cur) {                    // rare: <=127 times total
            int sv0 = seg[n];
            if (sv0 != cur) { FLUSH(cur); cur = sv0; }
            aS += e0;
            aV0 = fmaf(e0, p00, aV0);
            aV1 = fmaf(e0, p10, aV1);
            if (sv1 != cur) { FLUSH(cur); cur = sv1; }
            aS += e1;
            aV0 = fmaf(e1, p01, aV0);
            aV1 = fmaf(e1, p11, aV1);
        } else {                             // hot path
            aS += e0 + e1;
            aV0 = fmaf(e0, p00, fmaf(e1, p01, aV0));
            aV1 = fmaf(e0, p10, fmaf(e1, p11, aV1));
        }
    }

    // ---- tail (at most 1 node) ----
    for (; n < end; n++) {
        const float4* row = base + (size_t)n * 64 + lane * 2;
        float4 xa = row[0];
        float4 xb = row[1];
        int s = seg[n];

        float x[8] = {xa.x, xa.y, xa.z, xa.w, xb.x, xb.y, xb.z, xb.w};
        float g = 0.f, p0 = 0.f, p1 = 0.f;
#pragma unroll
        for (int j = 0; j < 8; j++) {
            g  = fmaf(x[j], wg [j], g);
            p0 = fmaf(x[j], wo0[j], p0);
            p1 = fmaf(x[j], wo1[j], p1);
        }
#pragma unroll
        for (int off = 16; off; off >>= 1)
            g += __shfl_xor_sync(0xFFFFFFFFu, g, off);

        float e = __expf(g + bgv);
        if (s != cur) { FLUSH(cur); cur = s; }
        aS += e;
        aV0 = fmaf(e, p0, aV0);
        aV1 = fmaf(e, p1, aV1);
    }

    FLUSH(cur);
#undef FLUSH
}

__global__ void ga_finalize(float* __restrict__ out, int B) {
    int b = blockIdx.x * blockDim.x + threadIdx.x;
    if (b < B) {
        float s  = g_accS [b];
        float v0 = g_accV0[b];
        float v1 = g_accV1[b];
        float d  = s + 1e-16f;
        out[2 * b + 0] = v0 / d;
        out[2 * b + 1] = v1 / d;
        // restore the "accumulators are zero" invariant for the next call
        g_accS [b] = 0.0f;
        g_accV0[b] = 0.0f;
        g_accV1[b] = 0.0f;
    }
}

extern "C" void kernel_launch(void* const* d_in, const int* in_sizes, int n_in,
                              void* d_out, int out_size)
{
    const float* states = (const float*)d_in[0];
    const int*   seg    = (const int*)  d_in[1];
    const float* Wg     = (const float*)d_in[2];
    const float* bg     = (const float*)d_in[3];
    const float* Wo     = (const float*)d_in[4];
    const float* bo     = (const float*)d_in[5];
    float*       out    = (float*)d_out;

    const int N = in_sizes[1];
    const int B = out_size / 2;

    ga_main<<<NBLOCKS, NTHREADS>>>(states, seg, Wg, bg, Wo, bo, N);
    ga_finalize<<<(B + 255) / 256, 256>>>(out, B);
}